// round 2
// baseline (speedup 1.0000x reference)
#include <cuda_runtime.h>
#include <cstdint>
#include <math.h>

#define NST    512
#define NOBS   1024
#define NBATCH 64
#define TMAX   512

#define RANKS   8      // CTAs per cluster (i-tiles)
#define ITILE   64     // states per CTA
#define NB      4      // batches per cluster
#define NGRP    16     // clusters
#define THREADS 512
#define KSL     8      // k-slices per CTA
#define KPS     64     // k per slice

// ---- shared memory layout (in floats) ----
#define OFF_AT   0                      // [512][64]  = 32768
#define OFF_P    32768                  // [2][512][4]= 4096
#define OFF_RED  36864                  // [8][4][64] = 2048
#define OFF_XR   38912                  // int [4][512]
#define OFF_MAXB 40960                  // [2][8][4]
#define OFF_MCUR 41024                  // [4]
#define OFF_WRED 41028                  // [8]
#define OFF_SRED 41036                  // [16]
#define OFF_TB   41052                  // int [4]
#define SMEM_FLOATS 41056
#define SMEM_BYTES  (SMEM_FLOATS * 4)

// ---- device scratch (allowed: static __device__ arrays) ----
__device__ float g_At[NST * NST];      // [k][i] = P(i | k) = softmax_i(A[:,k])
__device__ float g_logEt[NOBS * NST];  // [m][i] = log_softmax_m(E[i,:])
__device__ float g_logpi[NST];

// ======================= helpers =======================

__device__ __forceinline__ float warpMax(float v) {
#pragma unroll
    for (int o = 16; o > 0; o >>= 1) v = fmaxf(v, __shfl_xor_sync(0xffffffffu, v, o));
    return v;
}
__device__ __forceinline__ float warpSum(float v) {
#pragma unroll
    for (int o = 16; o > 0; o >>= 1) v += __shfl_xor_sync(0xffffffffu, v, o);
    return v;
}

// block of 512 threads (16 warps)
__device__ __forceinline__ float blockMax512(float v, float* sc) {
    float w = warpMax(v);
    int wid = threadIdx.x >> 5;
    if ((threadIdx.x & 31) == 0) sc[wid] = w;
    __syncthreads();
    if (threadIdx.x < 32) {
        float x = (threadIdx.x < 16) ? sc[threadIdx.x] : -INFINITY;
        x = warpMax(x);
        if (threadIdx.x == 0) sc[0] = x;
    }
    __syncthreads();
    float r = sc[0];
    __syncthreads();
    return r;
}
__device__ __forceinline__ float blockSum512(float v, float* sc) {
    float w = warpSum(v);
    int wid = threadIdx.x >> 5;
    if ((threadIdx.x & 31) == 0) sc[wid] = w;
    __syncthreads();
    if (threadIdx.x < 32) {
        float x = (threadIdx.x < 16) ? sc[threadIdx.x] : 0.0f;
        x = warpSum(x);
        if (threadIdx.x == 0) sc[0] = x;
    }
    __syncthreads();
    float r = sc[0];
    __syncthreads();
    return r;
}

__device__ __forceinline__ uint32_t smem_u32(const void* p) {
    return (uint32_t)__cvta_generic_to_shared(p);
}
__device__ __forceinline__ uint32_t mapa_u32(uint32_t a, uint32_t rank) {
    uint32_t d;
    asm("mapa.shared::cluster.u32 %0, %1, %2;" : "=r"(d) : "r"(a), "r"(rank));
    return d;
}
__device__ __forceinline__ void st_cluster_f32(uint32_t a, float v) {
    asm volatile("st.shared::cluster.f32 [%0], %1;" :: "r"(a), "f"(v) : "memory");
}
__device__ __forceinline__ void st_cluster_v4(uint32_t a, float4 v) {
    asm volatile("st.shared::cluster.v4.f32 [%0], {%1,%2,%3,%4};"
                 :: "r"(a), "f"(v.x), "f"(v.y), "f"(v.z), "f"(v.w) : "memory");
}
__device__ __forceinline__ void cluster_arrive() {
    asm volatile("barrier.cluster.arrive.aligned;" ::: "memory");
}
__device__ __forceinline__ void cluster_wait() {
    asm volatile("barrier.cluster.wait.aligned;" ::: "memory");
}

// ======================= prep kernels =======================

// log_pi[i] = pi[i] - logsumexp(pi)
__global__ void k_logpi(const float* __restrict__ pi) {
    __shared__ float sc[16];
    int t = threadIdx.x;
    float v = pi[t];
    float m = blockMax512(v, sc);
    float s = blockSum512(__expf(v - m), sc);
    g_logpi[t] = v - m - __logf(s);
}

// column-softmax of A; write transposed: g_At[k*512 + i] = exp(A[i,k]-m)/sum
__global__ void k_prepA(const float* __restrict__ A) {
    __shared__ float sc[16];
    int k = blockIdx.x;
    int i = threadIdx.x;
    float a = A[i * NST + k];
    float m = blockMax512(a, sc);
    float e = __expf(a - m);
    float s = blockSum512(e, sc);
    g_At[k * NST + i] = e / s;
}

// row log-softmax of E; write transposed: g_logEt[m*512 + i] = E[i,m] - lse_row
__global__ void k_prepE(const float* __restrict__ E) {
    __shared__ float sc[16];
    int i = blockIdx.x;
    int t = threadIdx.x;
    float a0 = E[i * NOBS + t];
    float a1 = E[i * NOBS + t + 512];
    float m = blockMax512(fmaxf(a0, a1), sc);
    float s = blockSum512(__expf(a0 - m) + __expf(a1 - m), sc);
    float lse = m + __logf(s);
    g_logEt[t * NST + i] = a0 - lse;
    g_logEt[(t + 512) * NST + i] = a1 - lse;
}

// ======================= main kernel =======================
// grid = 128 CTAs, clusters of 8. Cluster g handles batches [4g,4g+4);
// CTA rank r owns states [64r, 64r+64) and keeps its A_prob slice in smem.

__global__ void __launch_bounds__(THREADS, 1) __cluster_dims__(RANKS, 1, 1)
hmm_main(const int* __restrict__ x, const int* __restrict__ Tarr,
         float* __restrict__ out)
{
    extern __shared__ float sm[];
    float* At_s   = sm + OFF_AT;     // [k][i_loc]
    float* p_s    = sm + OFF_P;      // [buf][k][b]
    float* red    = sm + OFF_RED;    // [ks][b][i_loc]
    int*   xr     = (int*)(sm + OFF_XR);
    float* maxbuf = sm + OFF_MAXB;   // [buf][rank][b]
    float* m_cur  = sm + OFF_MCUR;   // [b]
    float* wred   = sm + OFF_WRED;   // [8]
    float* sred   = sm + OFF_SRED;   // [16]
    int*   Tb     = (int*)(sm + OFF_TB);

    const int tid   = threadIdx.x;
    const int rank  = blockIdx.x & (RANKS - 1);
    const int grp   = blockIdx.x >> 3;
    const int i_loc = tid & (ITILE - 1);
    const int ks    = tid >> 6;               // 0..7
    const int i_glob = rank * ITILE + i_loc;

    // --- load A_prob slice into smem: At_s[k][i_loc] = g_At[k*512 + i_glob]
    for (int idx = tid; idx < NST * (ITILE / 4); idx += THREADS) {
        int k = idx >> 4, v = idx & 15;
        float4 val = *(const float4*)(&g_At[k * NST + rank * ITILE + v * 4]);
        *(float4*)(&At_s[k * ITILE + v * 4]) = val;
    }
    // --- observations & lengths for this cluster's 4 batches
    for (int idx = tid; idx < NB * TMAX; idx += THREADS) {
        int b = idx >> 9, t = idx & (TMAX - 1);
        xr[b * TMAX + t] = x[(grp * NB + b) * TMAX + t];
    }
    if (tid < NB) Tb[tid] = Tarr[grp * NB + tid];
    __syncthreads();

    // --- alpha0: threads with ks<4 own (b=ks, i_loc)
    const int myb = ks;
    float alpha = 0.0f;
    if (ks < NB) {
        int obs = xr[myb * TMAX + 0];
        alpha = g_logpi[i_glob] + g_logEt[obs * NST + i_glob];
    }

    // --- initial max exchange (exact max of alpha0) into maxbuf[0]
    {
        if (ks < NB) {
            float wm = warpMax(alpha);
            if ((tid & 31) == 0) wred[tid >> 5] = wm;
        }
        __syncthreads();
        if (tid < NB) {
            float lm = fmaxf(wred[2 * tid], wred[2 * tid + 1]);
            maxbuf[rank * NB + tid] = lm;
            uint32_t laddr = smem_u32(&maxbuf[rank * NB + tid]);
            for (int r = 0; r < RANKS; r++)
                if (r != rank) st_cluster_f32(mapa_u32(laddr, r), lm);
        }
        cluster_arrive(); cluster_wait();
        if (tid < NB) {
            float m = -INFINITY;
            for (int r = 0; r < RANKS; r++) m = fmaxf(m, maxbuf[r * NB + tid]);
            m_cur[tid] = m;
        }
        __syncthreads();
    }

    // ===================== time loop =====================
    for (int t = 1; t <= TMAX; t++) {
        const int buf = t & 1;
        float* pb = p_s + buf * (NST * NB);

        // (1) capture shift values (consistent cluster-wide, pre-update)
        float mu0 = m_cur[0], mu1 = m_cur[1], mu2 = m_cur[2], mu3 = m_cur[3];

        // (2) p = exp(alpha - mu); local store + warp maxes of alpha
        if (ks < NB) {
            float mu = (myb == 0) ? mu0 : (myb == 1) ? mu1 : (myb == 2) ? mu2 : mu3;
            float pv = __expf(alpha - mu);
            pb[i_glob * NB + myb] = pv;
            float wm = warpMax(alpha);
            if ((tid & 31) == 0) wred[tid >> 5] = wm;
        }
        __syncthreads();

        // (3) push my p-chunk (64 rows x float4) + local maxes to the 7 peers
        {
            uint32_t lbase = smem_u32(&pb[rank * ITILE * NB]);
            for (int idx = tid; idx < (RANKS - 1) * ITILE; idx += THREADS) {
                int pr = idx >> 6;
                int peer = pr + (pr >= rank);
                int row = idx & (ITILE - 1);
                float4 v = *(const float4*)(&pb[(rank * ITILE + row) * NB]);
                st_cluster_v4(mapa_u32(lbase + row * 16, peer), v);
            }
            if (tid < NB) {
                float lm = fmaxf(wred[2 * tid], wred[2 * tid + 1]);
                maxbuf[buf * (RANKS * NB) + rank * NB + tid] = lm;
                uint32_t laddr = smem_u32(&maxbuf[buf * (RANKS * NB) + rank * NB + tid]);
                for (int r = 0; r < RANKS; r++)
                    if (r != rank) st_cluster_f32(mapa_u32(laddr, r), lm);
            }
        }
        cluster_arrive(); cluster_wait();

        // (4) update shift for NEXT iteration (stale by one step; safe bound)
        if (tid < NB) {
            float m = -INFINITY;
            for (int r = 0; r < RANKS; r++)
                m = fmaxf(m, maxbuf[buf * (RANKS * NB) + r * NB + tid]);
            m_cur[tid] = m;
        }

        // (5) emissions: p corresponds to alpha_{t-1}; answer when t == T[b]
#pragma unroll
        for (int b = 0; b < NB; b++) {
            if (Tb[b] == t) {
                float part = pb[tid * NB + b];       // tid == k
                float ws = warpSum(part);
                if ((tid & 31) == 0) sred[tid >> 5] = ws;
                __syncthreads();
                if (tid == 0 && rank == 0) {
                    float s = 0.0f;
#pragma unroll
                    for (int w = 0; w < 16; w++) s += sred[w];
                    float mu = (b == 0) ? mu0 : (b == 1) ? mu1 : (b == 2) ? mu2 : mu3;
                    out[grp * NB + b] = mu + __logf(s);
                }
                __syncthreads();
            }
        }

        // (6) recurrence: s[b,i] = sum_k At[k][i] * p[k][b], split over k-slices
        if (t < TMAX) {
            const float*  Ab  = At_s + (ks * KPS) * ITILE + i_loc;
            const float4* Pb4 = (const float4*)pb + ks * KPS;
            float s0 = 0.f, s1 = 0.f, s2 = 0.f, s3 = 0.f;
#pragma unroll 16
            for (int kk = 0; kk < KPS; kk++) {
                float a = Ab[kk * ITILE];
                float4 p4 = Pb4[kk];
                s0 = fmaf(a, p4.x, s0);
                s1 = fmaf(a, p4.y, s1);
                s2 = fmaf(a, p4.z, s2);
                s3 = fmaf(a, p4.w, s3);
            }
            red[(ks * NB + 0) * ITILE + i_loc] = s0;
            red[(ks * NB + 1) * ITILE + i_loc] = s1;
            red[(ks * NB + 2) * ITILE + i_loc] = s2;
            red[(ks * NB + 3) * ITILE + i_loc] = s3;
            __syncthreads();
            if (ks < NB) {
                float tot = 0.f;
#pragma unroll
                for (int q = 0; q < KSL; q++)
                    tot += red[(q * NB + myb) * ITILE + i_loc];
                int obs = xr[myb * TMAX + t];
                float em = g_logEt[obs * NST + i_glob];
                float mu = (myb == 0) ? mu0 : (myb == 1) ? mu1 : (myb == 2) ? mu2 : mu3;
                alpha = __logf(fmaxf(tot, 1e-37f)) + mu + em;
            }
            __syncthreads();   // red/wred/m_cur reuse ordering before next iter
        }
    }
}

// ======================= launch =======================

extern "C" void kernel_launch(void* const* d_in, const int* in_sizes, int n_in,
                              void* d_out, int out_size)
{
    const float* pi = (const float*)d_in[0];
    const float* A  = (const float*)d_in[1];
    const float* E  = (const float*)d_in[2];
    const int*   x  = (const int*)d_in[3];
    const int*   T  = (const int*)d_in[4];
    float* out = (float*)d_out;

    cudaFuncSetAttribute(hmm_main, cudaFuncAttributeMaxDynamicSharedMemorySize,
                         SMEM_BYTES);

    k_logpi<<<1, 512>>>(pi);
    k_prepA<<<NST, 512>>>(A);
    k_prepE<<<NST, 512>>>(E);
    hmm_main<<<NGRP * RANKS, THREADS, SMEM_BYTES>>>(x, T, out);
}

// round 5
// speedup vs baseline: 1.2847x; 1.2847x over previous
#include <cuda_runtime.h>
#include <cstdint>
#include <math.h>

#define NST    512
#define NOBS   1024
#define NBATCH 64
#define TMAX   512

#define RANKS   8      // CTAs per cluster (i-tiles)
#define ITILE   64     // states per CTA
#define NB      4      // batches per cluster
#define NGRP    16     // clusters
#define THREADS 512

// ---- shared memory layout (in floats) ----
#define OFF_AT   0                      // [512][64]      = 32768
#define OFF_P    32768                  // [2][512][4]    = 4096
#define OFF_RED  36864                  // [4][512*4]     = 8192
#define OFF_XR   45056                  // int [4][512]   = 2048
#define OFF_MAXB 47104                  // [2][8][4]      = 64
#define OFF_MCUR 47168                  // [4]
#define OFF_WRED 47172                  // [8][4] = 32
#define OFF_SRED 47204                  // [16]
#define OFF_TB   47220                  // int [4]
#define SMEM_FLOATS 47224
#define SMEM_BYTES  (SMEM_FLOATS * 4)

typedef unsigned long long ull;

// ---- device scratch ----
__device__ float g_At[NST * NST];      // [k][i] = P(i | k) = softmax_i(A[:,k])
__device__ float g_logEt[NOBS * NST];  // [m][i] = log_softmax_m(E[i,:])
__device__ float g_logpi[NST];

// ======================= helpers =======================

__device__ __forceinline__ float warpMax(float v) {
#pragma unroll
    for (int o = 16; o > 0; o >>= 1) v = fmaxf(v, __shfl_xor_sync(0xffffffffu, v, o));
    return v;
}
__device__ __forceinline__ float warpSum(float v) {
#pragma unroll
    for (int o = 16; o > 0; o >>= 1) v += __shfl_xor_sync(0xffffffffu, v, o);
    return v;
}
__device__ __forceinline__ float blockMax512(float v, float* sc) {
    float w = warpMax(v);
    int wid = threadIdx.x >> 5;
    if ((threadIdx.x & 31) == 0) sc[wid] = w;
    __syncthreads();
    if (threadIdx.x < 32) {
        float x = (threadIdx.x < 16) ? sc[threadIdx.x] : -INFINITY;
        x = warpMax(x);
        if (threadIdx.x == 0) sc[0] = x;
    }
    __syncthreads();
    float r = sc[0];
    __syncthreads();
    return r;
}
__device__ __forceinline__ float blockSum512(float v, float* sc) {
    float w = warpSum(v);
    int wid = threadIdx.x >> 5;
    if ((threadIdx.x & 31) == 0) sc[wid] = w;
    __syncthreads();
    if (threadIdx.x < 32) {
        float x = (threadIdx.x < 16) ? sc[threadIdx.x] : 0.0f;
        x = warpSum(x);
        if (threadIdx.x == 0) sc[0] = x;
    }
    __syncthreads();
    float r = sc[0];
    __syncthreads();
    return r;
}

__device__ __forceinline__ uint32_t smem_u32(const void* p) {
    return (uint32_t)__cvta_generic_to_shared(p);
}
__device__ __forceinline__ uint32_t mapa_u32(uint32_t a, uint32_t rank) {
    uint32_t d;
    asm("mapa.shared::cluster.u32 %0, %1, %2;" : "=r"(d) : "r"(a), "r"(rank));
    return d;
}
__device__ __forceinline__ void st_cluster_f32(uint32_t a, float v) {
    asm volatile("st.shared::cluster.f32 [%0], %1;" :: "r"(a), "f"(v) : "memory");
}
__device__ __forceinline__ void st_cluster_v4(uint32_t a, float4 v) {
    asm volatile("st.shared::cluster.v4.f32 [%0], {%1,%2,%3,%4};"
                 :: "r"(a), "f"(v.x), "f"(v.y), "f"(v.z), "f"(v.w) : "memory");
}
__device__ __forceinline__ void cluster_arrive() {
    asm volatile("barrier.cluster.arrive.aligned;" ::: "memory");
}
__device__ __forceinline__ void cluster_wait() {
    asm volatile("barrier.cluster.wait.aligned;" ::: "memory");
}

// ---- packed f32x2 FMA ----
__device__ __forceinline__ void ffma2(ull& d, ull a, ull b) {
    asm("fma.rn.f32x2 %0, %1, %2, %0;" : "+l"(d) : "l"(a), "l"(b));
}
__device__ __forceinline__ ull dup2(float p) {
    ull r; uint32_t u = __float_as_uint(p);
    asm("mov.b64 %0, {%1, %1};" : "=l"(r) : "r"(u));
    return r;
}
__device__ __forceinline__ void unpk(ull v, float& lo, float& hi) {
    uint32_t a, b;
    asm("mov.b64 {%0, %1}, %2;" : "=r"(a), "=r"(b) : "l"(v));
    lo = __uint_as_float(a); hi = __uint_as_float(b);
}

// ======================= prep kernels =======================

__global__ void k_logpi(const float* __restrict__ pi) {
    __shared__ float sc[16];
    int t = threadIdx.x;
    float v = pi[t];
    float m = blockMax512(v, sc);
    float s = blockSum512(__expf(v - m), sc);
    g_logpi[t] = v - m - __logf(s);
}

__global__ void k_prepA(const float* __restrict__ A) {
    __shared__ float sc[16];
    int k = blockIdx.x;
    int i = threadIdx.x;
    float a = A[i * NST + k];
    float m = blockMax512(a, sc);
    float e = __expf(a - m);
    float s = blockSum512(e, sc);
    g_At[k * NST + i] = e / s;
}

__global__ void k_prepE(const float* __restrict__ E) {
    __shared__ float sc[16];
    int i = blockIdx.x;
    int t = threadIdx.x;
    float a0 = E[i * NOBS + t];
    float a1 = E[i * NOBS + t + 512];
    float m = blockMax512(fmaxf(a0, a1), sc);
    float s = blockSum512(__expf(a0 - m) + __expf(a1 - m), sc);
    float lse = m + __logf(s);
    g_logEt[t * NST + i] = a0 - lse;
    g_logEt[(t + 512) * NST + i] = a1 - lse;
}

// ======================= main kernel =======================
// 16 clusters x 8 CTAs. Cluster g: batches [4g,4g+4); CTA rank r: states [64r,64r+64).
// Main-loop thread map: ks = tid>>4 (32 k-slices of 16), igm = tid&15 (16 i-groups of 4).
// Alpha/p owner map (tid<256): iv = tid>>6, ig = (tid&63)>>2, b = tid&3; i_loc = ig*4+iv.

__global__ void __launch_bounds__(THREADS, 1) __cluster_dims__(RANKS, 1, 1)
hmm_main(const int* __restrict__ x, const int* __restrict__ Tarr,
         float* __restrict__ out)
{
    extern __shared__ float sm[];
    float* At_s   = sm + OFF_AT;
    float* p_s    = sm + OFF_P;
    float* red    = sm + OFF_RED;     // [iv][ (ks*16+igm)*4 + b ]
    int*   xr     = (int*)(sm + OFF_XR);
    float* maxbuf = sm + OFF_MAXB;
    float* m_cur  = sm + OFF_MCUR;
    float* wred   = sm + OFF_WRED;    // [warp][b]
    float* sred   = sm + OFF_SRED;
    int*   Tb     = (int*)(sm + OFF_TB);

    const int tid  = threadIdx.x;
    const int rank = blockIdx.x & (RANKS - 1);
    const int grp  = blockIdx.x >> 3;

    // main-loop mapping
    const int ksl = tid >> 4;          // 0..31
    const int igm = tid & 15;          // 0..15

    // alpha/p owner mapping (tid < 256)
    const int iv   = tid >> 6;                 // 0..3
    const int igo  = (tid & 63) >> 2;          // 0..15
    const int myb  = tid & 3;                  // 0..3
    const int i_loc  = igo * 4 + iv;           // 0..63
    const int i_glob = rank * ITILE + i_loc;
    const int poff   = rank * 256 + i_loc * 4 + myb;   // index into pb
    const int rbase  = iv * 2048 + (tid & 63);         // phase-B read base (stride 64)

    // --- load A_prob slice: At_s[k*64 + i_loc] = g_At[k*512 + rank*64 + i_loc]
    for (int idx = tid; idx < NST * (ITILE / 4); idx += THREADS) {
        int k = idx >> 4, v = idx & 15;
        float4 val = *(const float4*)(&g_At[k * NST + rank * ITILE + v * 4]);
        *(float4*)(&At_s[k * ITILE + v * 4]) = val;
    }
    for (int idx = tid; idx < NB * TMAX; idx += THREADS) {
        int b = idx >> 9, t = idx & (TMAX - 1);
        xr[b * TMAX + t] = x[(grp * NB + b) * TMAX + t];
    }
    if (tid < NB) Tb[tid] = Tarr[grp * NB + tid];
    __syncthreads();

    // --- alpha0 + per-warp per-b max into wred
    float alpha = 0.0f;
    if (tid < 256) {
        int obs = xr[myb * TMAX + 0];
        alpha = g_logpi[i_glob] + g_logEt[obs * NST + i_glob];
        float m = alpha;
        m = fmaxf(m, __shfl_xor_sync(0xffffffffu, m, 4));
        m = fmaxf(m, __shfl_xor_sync(0xffffffffu, m, 8));
        m = fmaxf(m, __shfl_xor_sync(0xffffffffu, m, 16));
        if ((tid & 31) < 4) wred[(tid >> 5) * 4 + myb] = m;
    }
    __syncthreads();

    // --- initial max exchange
    if (tid < NB) {
        float lm = wred[tid];
#pragma unroll
        for (int w = 1; w < 8; w++) lm = fmaxf(lm, wred[w * 4 + tid]);
        maxbuf[rank * NB + tid] = lm;
        uint32_t laddr = smem_u32(&maxbuf[rank * NB + tid]);
        for (int r = 0; r < RANKS; r++)
            if (r != rank) st_cluster_f32(mapa_u32(laddr, r), lm);
    }
    cluster_arrive(); cluster_wait();
    if (tid < NB) {
        float m = -INFINITY;
        for (int r = 0; r < RANKS; r++) m = fmaxf(m, maxbuf[r * NB + tid]);
        m_cur[tid] = m;
    }
    __syncthreads();

    // ===================== time loop =====================
    for (int t = 1; t <= TMAX; t++) {
        const int buf = t & 1;
        float* pb = p_s + buf * (NST * NB);

        // (1) capture shift values (pre-update)
        float mu0 = m_cur[0], mu1 = m_cur[1], mu2 = m_cur[2], mu3 = m_cur[3];
        float mu_my = (myb == 0) ? mu0 : (myb == 1) ? mu1 : (myb == 2) ? mu2 : mu3;

        // (2) p = exp(alpha - mu)
        if (tid < 256) {
            pb[poff] = __expf(alpha - mu_my);
        }
        __syncthreads();

        // (3) push my p-chunk + per-rank maxes to the 7 peers
        {
            uint32_t lbase = smem_u32(&pb[rank * 256]);
            for (int idx = tid; idx < (RANKS - 1) * ITILE; idx += THREADS) {
                int pr = idx >> 6;
                int peer = pr + (pr >= rank);
                int row = idx & (ITILE - 1);
                float4 v = *(const float4*)(&pb[rank * 256 + row * 4]);
                st_cluster_v4(mapa_u32(lbase + row * 16, peer), v);
            }
            if (tid < NB) {
                float lm = wred[tid];
#pragma unroll
                for (int w = 1; w < 8; w++) lm = fmaxf(lm, wred[w * 4 + tid]);
                maxbuf[buf * (RANKS * NB) + rank * NB + tid] = lm;
                uint32_t laddr = smem_u32(&maxbuf[buf * (RANKS * NB) + rank * NB + tid]);
                for (int r = 0; r < RANKS; r++)
                    if (r != rank) st_cluster_f32(mapa_u32(laddr, r), lm);
            }
        }
        cluster_arrive(); cluster_wait();

        // (4) shift for NEXT step
        if (tid < NB) {
            float m = -INFINITY;
            for (int r = 0; r < RANKS; r++)
                m = fmaxf(m, maxbuf[buf * (RANKS * NB) + r * NB + tid]);
            m_cur[tid] = m;
        }

        // (5) emission: pb corresponds to alpha_{t-1}; answer when t == T[b]
#pragma unroll
        for (int b = 0; b < NB; b++) {
            if (Tb[b] == t) {
                float part = pb[tid * NB + b];       // tid == k
                float ws = warpSum(part);
                if ((tid & 31) == 0) sred[tid >> 5] = ws;
                __syncthreads();
                if (tid == 0 && rank == 0) {
                    float s = 0.0f;
#pragma unroll
                    for (int w = 0; w < 16; w++) s += sred[w];
                    float mu = (b == 0) ? mu0 : (b == 1) ? mu1 : (b == 2) ? mu2 : mu3;
                    out[grp * NB + b] = mu + __logf(s);
                }
                __syncthreads();
            }
        }

        // (6) recurrence: s[i,b] = sum_k At[k][i] * p[k][b]
        if (t < TMAX) {
            // main loop: 16 k per slice, 4i x 4b per thread, FFMA2
            {
                const float* Ab = At_s + igm * 4;
                const float4* Pb4 = (const float4*)pb;
                ull a00 = 0, a01 = 0, a02 = 0, a03 = 0;  // ipair 0 (iv 0,1)
                ull a10 = 0, a11 = 0, a12 = 0, a13 = 0;  // ipair 1 (iv 2,3)
                const int k0 = ksl * 16;
#pragma unroll
                for (int kk = 0; kk < 16; kk++) {
                    int k = k0 + kk;
                    ulonglong2 a2 = *(const ulonglong2*)(Ab + k * ITILE);
                    float4 p4 = Pb4[k];
                    ull p0 = dup2(p4.x), p1 = dup2(p4.y);
                    ull p2 = dup2(p4.z), p3 = dup2(p4.w);
                    ffma2(a00, a2.x, p0); ffma2(a01, a2.x, p1);
                    ffma2(a02, a2.x, p2); ffma2(a03, a2.x, p3);
                    ffma2(a10, a2.y, p0); ffma2(a11, a2.y, p1);
                    ffma2(a12, a2.y, p2); ffma2(a13, a2.y, p3);
                }
                // phase A: coalesced stores red[iv*2048 + tid*4 + b]
                float l0, h0, l1, h1, l2, h2, l3, h3;
                unpk(a00, l0, h0); unpk(a01, l1, h1);
                unpk(a02, l2, h2); unpk(a03, l3, h3);
                *(float4*)(red + 0 * 2048 + tid * 4) = make_float4(l0, l1, l2, l3);
                *(float4*)(red + 1 * 2048 + tid * 4) = make_float4(h0, h1, h2, h3);
                unpk(a10, l0, h0); unpk(a11, l1, h1);
                unpk(a12, l2, h2); unpk(a13, l3, h3);
                *(float4*)(red + 2 * 2048 + tid * 4) = make_float4(l0, l1, l2, l3);
                *(float4*)(red + 3 * 2048 + tid * 4) = make_float4(h0, h1, h2, h3);
            }
            __syncthreads();

            // phase B: cross-slice reduce (1 wavefront per load), alpha update
            if (tid < 256) {
                const float* rb = red + rbase;
                float t0 = 0.f, t1 = 0.f, t2 = 0.f, t3 = 0.f;
#pragma unroll
                for (int q = 0; q < 8; q++) {
                    t0 += rb[(4 * q + 0) * 64];
                    t1 += rb[(4 * q + 1) * 64];
                    t2 += rb[(4 * q + 2) * 64];
                    t3 += rb[(4 * q + 3) * 64];
                }
                float tot = (t0 + t1) + (t2 + t3);
                int obs = xr[myb * TMAX + t];
                float em = g_logEt[obs * NST + i_glob];
                alpha = __logf(fmaxf(tot, 1e-37f)) + mu_my + em;
                // per-warp per-b max for next step's exchange
                float m = alpha;
                m = fmaxf(m, __shfl_xor_sync(0xffffffffu, m, 4));
                m = fmaxf(m, __shfl_xor_sync(0xffffffffu, m, 8));
                m = fmaxf(m, __shfl_xor_sync(0xffffffffu, m, 16));
                if ((tid & 31) < 4) wred[(tid >> 5) * 4 + myb] = m;
            }
            __syncthreads();
        }
    }
}

// ======================= launch =======================

extern "C" void kernel_launch(void* const* d_in, const int* in_sizes, int n_in,
                              void* d_out, int out_size)
{
    const float* pi = (const float*)d_in[0];
    const float* A  = (const float*)d_in[1];
    const float* E  = (const float*)d_in[2];
    const int*   x  = (const int*)d_in[3];
    const int*   T  = (const int*)d_in[4];
    float* out = (float*)d_out;

    cudaFuncSetAttribute(hmm_main, cudaFuncAttributeMaxDynamicSharedMemorySize,
                         SMEM_BYTES);

    k_logpi<<<1, 512>>>(pi);
    k_prepA<<<NST, 512>>>(A);
    k_prepE<<<NST, 512>>>(E);
    hmm_main<<<NGRP * RANKS, THREADS, SMEM_BYTES>>>(x, T, out);
}

// round 6
// speedup vs baseline: 2.6659x; 2.0752x over previous
#include <cuda_runtime.h>
#include <cstdint>
#include <math.h>

#define NST    512
#define NOBS   1024
#define NBATCH 64
#define TMAX   512

#define RANKS   8      // CTAs per cluster (i-tiles)
#define ITILE   64     // states per CTA
#define NB      4      // batches per cluster
#define NGRP    16     // clusters
#define THREADS 512

// ---- shared memory layout (in floats) ----
#define OFF_AT   0                      // [512][64]      = 32768
#define OFF_P    32768                  // [2][512][4]    = 4096
#define OFF_RED  36864                  // [4][512*4]     = 8192
#define OFF_XR   45056                  // int [4][512]   = 2048
#define OFF_MAXB 47104                  // [2][8][4]      = 64
#define OFF_MUV  47168                  // [2][4]         = 8
#define OFF_WRED 47176                  // [8][4]         = 32
#define OFF_SRED 47208                  // [16]
#define OFF_TB   47224                  // int [4]
#define OFF_MBAR 47228                  // u64 mbarrier (8B aligned: 47228*4 % 8 == 0)
#define SMEM_FLOATS 47232
#define SMEM_BYTES  (SMEM_FLOATS * 4)

typedef unsigned long long ull;

// ---- device scratch ----
__device__ float g_At[NST * NST];      // [k][i] = P(i | k) = softmax_i(A[:,k])
__device__ float g_logEt[NOBS * NST];  // [m][i] = log_softmax_m(E[i,:])
__device__ float g_logpi[NST];

// ======================= helpers =======================

__device__ __forceinline__ float warpMax(float v) {
#pragma unroll
    for (int o = 16; o > 0; o >>= 1) v = fmaxf(v, __shfl_xor_sync(0xffffffffu, v, o));
    return v;
}
__device__ __forceinline__ float warpSum(float v) {
#pragma unroll
    for (int o = 16; o > 0; o >>= 1) v += __shfl_xor_sync(0xffffffffu, v, o);
    return v;
}
__device__ __forceinline__ float blockMax512(float v, float* sc) {
    float w = warpMax(v);
    int wid = threadIdx.x >> 5;
    if ((threadIdx.x & 31) == 0) sc[wid] = w;
    __syncthreads();
    if (threadIdx.x < 32) {
        float x = (threadIdx.x < 16) ? sc[threadIdx.x] : -INFINITY;
        x = warpMax(x);
        if (threadIdx.x == 0) sc[0] = x;
    }
    __syncthreads();
    float r = sc[0];
    __syncthreads();
    return r;
}
__device__ __forceinline__ float blockSum512(float v, float* sc) {
    float w = warpSum(v);
    int wid = threadIdx.x >> 5;
    if ((threadIdx.x & 31) == 0) sc[wid] = w;
    __syncthreads();
    if (threadIdx.x < 32) {
        float x = (threadIdx.x < 16) ? sc[threadIdx.x] : 0.0f;
        x = warpSum(x);
        if (threadIdx.x == 0) sc[0] = x;
    }
    __syncthreads();
    float r = sc[0];
    __syncthreads();
    return r;
}

__device__ __forceinline__ uint32_t smem_u32(const void* p) {
    return (uint32_t)__cvta_generic_to_shared(p);
}
__device__ __forceinline__ uint32_t mapa_u32(uint32_t a, uint32_t rank) {
    uint32_t d;
    asm("mapa.shared::cluster.u32 %0, %1, %2;" : "=r"(d) : "r"(a), "r"(rank));
    return d;
}
__device__ __forceinline__ void st_cluster_f32(uint32_t a, float v) {
    asm volatile("st.shared::cluster.f32 [%0], %1;" :: "r"(a), "f"(v) : "memory");
}
__device__ __forceinline__ void st_cluster_v4(uint32_t a, float4 v) {
    asm volatile("st.shared::cluster.v4.f32 [%0], {%1,%2,%3,%4};"
                 :: "r"(a), "f"(v.x), "f"(v.y), "f"(v.z), "f"(v.w) : "memory");
}
__device__ __forceinline__ void cluster_arrive() {
    asm volatile("barrier.cluster.arrive.aligned;" ::: "memory");
}
__device__ __forceinline__ void cluster_wait() {
    asm volatile("barrier.cluster.wait.aligned;" ::: "memory");
}

// ---- mbarrier ops ----
__device__ __forceinline__ void mbar_init(uint32_t a, uint32_t cnt) {
    asm volatile("mbarrier.init.shared.b64 [%0], %1;" :: "r"(a), "r"(cnt) : "memory");
}
__device__ __forceinline__ void mbar_arrive_local(uint32_t a) {
    asm volatile("mbarrier.arrive.shared.b64 _, [%0];" :: "r"(a) : "memory");
}
__device__ __forceinline__ void mbar_arrive_peer(uint32_t a, uint32_t peer) {
    asm volatile(
        "{\n\t.reg .b32 ra;\n\t"
        "mapa.shared::cluster.u32 ra, %0, %1;\n\t"
        "mbarrier.arrive.shared::cluster.b64 _, [ra];\n\t}"
        :: "r"(a), "r"(peer) : "memory");
}
__device__ __forceinline__ void mbar_wait_parity(uint32_t a, uint32_t ph) {
    uint32_t done;
    asm volatile(
        "{\n\t.reg .pred p;\n\t"
        "mbarrier.try_wait.parity.acquire.cta.shared::cta.b64 p, [%1], %2;\n\t"
        "selp.b32 %0, 1, 0, p;\n\t}"
        : "=r"(done) : "r"(a), "r"(ph) : "memory");
    if (!done) {
        asm volatile(
            "{\n\t.reg .pred P1;\n\t"
            "WL_%=:\n\t"
            "mbarrier.try_wait.parity.acquire.cta.shared::cta.b64 P1, [%0], %1, 0x989680;\n\t"
            "@P1 bra.uni WD_%=;\n\t"
            "bra.uni WL_%=;\n\t"
            "WD_%=:\n\t}"
            :: "r"(a), "r"(ph) : "memory");
    }
}

// ---- packed f32x2 FMA ----
__device__ __forceinline__ void ffma2(ull& d, ull a, ull b) {
    asm("fma.rn.f32x2 %0, %1, %2, %0;" : "+l"(d) : "l"(a), "l"(b));
}
__device__ __forceinline__ ull dup2(float p) {
    ull r; uint32_t u = __float_as_uint(p);
    asm("mov.b64 %0, {%1, %1};" : "=l"(r) : "r"(u));
    return r;
}
__device__ __forceinline__ void unpk(ull v, float& lo, float& hi) {
    uint32_t a, b;
    asm("mov.b64 {%0, %1}, %2;" : "=r"(a), "=r"(b) : "l"(v));
    lo = __uint_as_float(a); hi = __uint_as_float(b);
}

// ======================= prep kernels =======================

__global__ void k_logpi(const float* __restrict__ pi) {
    __shared__ float sc[16];
    int t = threadIdx.x;
    float v = pi[t];
    float m = blockMax512(v, sc);
    float s = blockSum512(__expf(v - m), sc);
    g_logpi[t] = v - m - __logf(s);
}

__global__ void k_prepA(const float* __restrict__ A) {
    __shared__ float sc[16];
    int k = blockIdx.x;
    int i = threadIdx.x;
    float a = A[i * NST + k];
    float m = blockMax512(a, sc);
    float e = __expf(a - m);
    float s = blockSum512(e, sc);
    g_At[k * NST + i] = e / s;
}

__global__ void k_prepE(const float* __restrict__ E) {
    __shared__ float sc[16];
    int i = blockIdx.x;
    int t = threadIdx.x;
    float a0 = E[i * NOBS + t];
    float a1 = E[i * NOBS + t + 512];
    float m = blockMax512(fmaxf(a0, a1), sc);
    float s = blockSum512(__expf(a0 - m) + __expf(a1 - m), sc);
    float lse = m + __logf(s);
    g_logEt[t * NST + i] = a0 - lse;
    g_logEt[(t + 512) * NST + i] = a1 - lse;
}

// ======================= main kernel =======================
// 16 clusters x 8 CTAs. Cluster g: batches [4g,4g+4); CTA rank r: states [64r,64r+64).
// Per step: mbarrier wait (data ready) -> FMA -> sync -> phase B -> sync -> push+arrive.

__global__ void __launch_bounds__(THREADS, 1) __cluster_dims__(RANKS, 1, 1)
hmm_main(const int* __restrict__ x, const int* __restrict__ Tarr,
         float* __restrict__ out)
{
    extern __shared__ float sm[];
    float* At_s   = sm + OFF_AT;
    float* p_s    = sm + OFF_P;      // [2][512][4]
    float* red    = sm + OFF_RED;
    int*   xr     = (int*)(sm + OFF_XR);
    float* maxbuf = sm + OFF_MAXB;   // [2][8][4]
    float* muv    = sm + OFF_MUV;    // [2][4]
    float* wred   = sm + OFF_WRED;   // [8][4]
    float* sred   = sm + OFF_SRED;
    int*   Tb     = (int*)(sm + OFF_TB);
    const uint32_t mbar = smem_u32(sm + OFF_MBAR);

    const int tid  = threadIdx.x;
    const int rank = blockIdx.x & (RANKS - 1);
    const int grp  = blockIdx.x >> 3;
    const int wid  = tid >> 5;
    const int lane = tid & 31;

    // FMA mapping
    const int ksl = tid >> 4;          // 0..31
    const int igm = tid & 15;          // 0..15

    // alpha/p owner mapping (tid < 256)
    const int iv   = tid >> 6;
    const int igo  = (tid & 63) >> 2;
    const int myb  = tid & 3;
    const int i_loc  = igo * 4 + iv;
    const int i_glob = rank * ITILE + i_loc;
    const int poff   = rank * 256 + i_loc * 4 + myb;
    const int rbase  = iv * 2048 + (tid & 63);

    // --- load A_prob slice, observations, lengths
    for (int idx = tid; idx < NST * (ITILE / 4); idx += THREADS) {
        int k = idx >> 4, v = idx & 15;
        float4 val = *(const float4*)(&g_At[k * NST + rank * ITILE + v * 4]);
        *(float4*)(&At_s[k * ITILE + v * 4]) = val;
    }
    for (int idx = tid; idx < NB * TMAX; idx += THREADS) {
        int b = idx >> 9, tt = idx & (TMAX - 1);
        xr[b * TMAX + tt] = x[(grp * NB + b) * TMAX + tt];
    }
    if (tid < NB) Tb[tid] = Tarr[grp * NB + tid];
    if (tid == 0) mbar_init(mbar, 8);
    __syncthreads();
    cluster_arrive(); cluster_wait();   // mbarrier init visible cluster-wide

    // --- alpha0 + per-warp per-b maxes
    float alpha = 0.0f, mu_reg = 0.0f;
    if (tid < 256) {
        int obs = xr[myb * TMAX + 0];
        alpha = g_logpi[i_glob] + g_logEt[obs * NST + i_glob];
        float m = alpha;
        m = fmaxf(m, __shfl_xor_sync(0xffffffffu, m, 4));
        m = fmaxf(m, __shfl_xor_sync(0xffffffffu, m, 8));
        m = fmaxf(m, __shfl_xor_sync(0xffffffffu, m, 16));
        if (lane < 4) wred[wid * 4 + myb] = m;
    }
    __syncthreads();

    // --- exchange alpha0 maxes exactly (one-time, cluster barrier ok)
    if (tid < NB) {
        float lm = wred[tid];
#pragma unroll
        for (int w = 1; w < 8; w++) lm = fmaxf(lm, wred[w * 4 + tid]);
        maxbuf[32 + rank * NB + tid] = lm;                     // buf=1
        uint32_t la = smem_u32(&maxbuf[32 + rank * NB + tid]);
        for (int r = 0; r < RANKS; r++)
            if (r != rank) st_cluster_f32(mapa_u32(la, r), lm);
    }
    cluster_arrive(); cluster_wait();

    const int Tlim = max(max(Tb[0], Tb[1]), max(Tb[2], Tb[3]));

    // --- p0 into buf 1
    {
        float* pb1 = p_s + 2048;
        if (tid < 256) {
            float mu0 = maxbuf[32 + myb];
#pragma unroll
            for (int r = 1; r < 8; r++) mu0 = fmaxf(mu0, maxbuf[32 + r * 4 + myb]);
            mu_reg = mu0;
            pb1[poff] = __expf(alpha - mu0);
            if (tid < 4) muv[4 + myb] = mu0;
        }
    }
    __syncthreads();

    // --- init push (phase 0): warps 0-6 push to peers; warp 7 local arrive
    {
        float* pbn = p_s + 2048;
        if (wid < 7) {
            int peer = wid + (wid >= rank);
            uint32_t lbase = smem_u32(&pbn[rank * 256]);
            uint32_t rb0 = mapa_u32(lbase, peer);
            float4 v0 = *(const float4*)(&pbn[rank * 256 + lane * 4]);
            float4 v1 = *(const float4*)(&pbn[rank * 256 + (lane + 32) * 4]);
            st_cluster_v4(rb0 + lane * 16, v0);
            st_cluster_v4(rb0 + (lane + 32) * 16, v1);
            __syncwarp();
            if (lane == 0) mbar_arrive_peer(mbar, peer);
        } else if (wid == 7) {
            __syncwarp();
            if (lane == 0) mbar_arrive_local(mbar);
        }
    }

    // ===================== time loop =====================
    for (int t = 1; t <= Tlim; t++) {
        const int buf = t & 1;
        float* pb = p_s + buf * 2048;

        // emission-logprob prefetch (independent of exchanged data: issue BEFORE wait)
        float em = 0.0f;
        if (tid < 256 && t < Tlim) {
            int obs = xr[myb * TMAX + t];
            em = g_logEt[obs * NST + i_glob];
        }

        // wait for all 8 p-chunks (+maxes) of this step
        mbar_wait_parity(mbar, (t - 1) & 1);

        // emission output: pb holds p(alpha_{t-1}); answer when t == T[b]
#pragma unroll
        for (int b = 0; b < NB; b++) {
            if (Tb[b] == t) {
                float part = pb[tid * NB + b];       // tid == k
                float ws = warpSum(part);
                if (lane == 0) sred[wid] = ws;
                __syncthreads();
                if (tid == 0 && rank == 0) {
                    float s = 0.0f;
#pragma unroll
                    for (int w = 0; w < 16; w++) s += sred[w];
                    out[grp * NB + b] = muv[buf * 4 + b] + __logf(s);
                }
                __syncthreads();
            }
        }
        if (t == Tlim) break;

        // ---- FMA: s[i,b] = sum_k At[k][i] * p[k][b]  (4i x 4b per thread, FFMA2)
        {
            const float* Ab = At_s + igm * 4;
            const float4* Pb4 = (const float4*)pb;
            ull a00 = 0, a01 = 0, a02 = 0, a03 = 0;
            ull a10 = 0, a11 = 0, a12 = 0, a13 = 0;
            const int k0 = ksl * 16;
#pragma unroll
            for (int kk = 0; kk < 16; kk++) {
                int k = k0 + kk;
                ulonglong2 a2 = *(const ulonglong2*)(Ab + k * ITILE);
                float4 p4 = Pb4[k];
                ull p0 = dup2(p4.x), p1 = dup2(p4.y);
                ull p2 = dup2(p4.z), p3 = dup2(p4.w);
                ffma2(a00, a2.x, p0); ffma2(a01, a2.x, p1);
                ffma2(a02, a2.x, p2); ffma2(a03, a2.x, p3);
                ffma2(a10, a2.y, p0); ffma2(a11, a2.y, p1);
                ffma2(a12, a2.y, p2); ffma2(a13, a2.y, p3);
            }
            float l0, h0, l1, h1, l2, h2, l3, h3;
            unpk(a00, l0, h0); unpk(a01, l1, h1);
            unpk(a02, l2, h2); unpk(a03, l3, h3);
            *(float4*)(red + 0 * 2048 + tid * 4) = make_float4(l0, l1, l2, l3);
            *(float4*)(red + 1 * 2048 + tid * 4) = make_float4(h0, h1, h2, h3);
            unpk(a10, l0, h0); unpk(a11, l1, h1);
            unpk(a12, l2, h2); unpk(a13, l3, h3);
            *(float4*)(red + 2 * 2048 + tid * 4) = make_float4(l0, l1, l2, l3);
            *(float4*)(red + 3 * 2048 + tid * 4) = make_float4(h0, h1, h2, h3);
        }
        __syncthreads();

        // ---- phase B: reduce, alpha update, p for next step, maxes
        if (tid < 256) {
            const float* rb = red + rbase;
            float t0 = 0.f, t1 = 0.f, t2 = 0.f, t3 = 0.f;
#pragma unroll
            for (int q = 0; q < 8; q++) {
                t0 += rb[(4 * q + 0) * 64];
                t1 += rb[(4 * q + 1) * 64];
                t2 += rb[(4 * q + 2) * 64];
                t3 += rb[(4 * q + 3) * 64];
            }
            float tot = (t0 + t1) + (t2 + t3);
            alpha = __logf(fmaxf(tot, 1e-37f)) + mu_reg + em;

            // next shift = max of alpha_{t-1} (maxbuf[buf], received this step)
            float mun = maxbuf[buf * 32 + myb];
#pragma unroll
            for (int r = 1; r < 8; r++)
                mun = fmaxf(mun, maxbuf[buf * 32 + r * 4 + myb]);

            float* pbn = p_s + (buf ^ 1) * 2048;
            pbn[poff] = __expf(alpha - mun);
            mu_reg = mun;
            if (tid < 4) muv[(buf ^ 1) * 4 + myb] = mun;

            float m = alpha;
            m = fmaxf(m, __shfl_xor_sync(0xffffffffu, m, 4));
            m = fmaxf(m, __shfl_xor_sync(0xffffffffu, m, 8));
            m = fmaxf(m, __shfl_xor_sync(0xffffffffu, m, 16));
            if (lane < 4) wred[wid * 4 + myb] = m;
        }
        __syncthreads();

        // ---- push p(alpha_t) + maxes to peers; arrive
        {
            const int bn = buf ^ 1;
            float* pbn = p_s + bn * 2048;
            if (wid < 7) {
                int peer = wid + (wid >= rank);
                uint32_t lbase = smem_u32(&pbn[rank * 256]);
                uint32_t rb0 = mapa_u32(lbase, peer);
                float4 v0 = *(const float4*)(&pbn[rank * 256 + lane * 4]);
                float4 v1 = *(const float4*)(&pbn[rank * 256 + (lane + 32) * 4]);
                st_cluster_v4(rb0 + lane * 16, v0);
                st_cluster_v4(rb0 + (lane + 32) * 16, v1);
                if (lane < 4) {
                    float lm = wred[lane];
#pragma unroll
                    for (int w = 1; w < 8; w++) lm = fmaxf(lm, wred[w * 4 + lane]);
                    uint32_t ma = smem_u32(&maxbuf[bn * 32 + rank * 4 + lane]);
                    st_cluster_f32(mapa_u32(ma, peer), lm);
                }
                __syncwarp();
                if (lane == 0) mbar_arrive_peer(mbar, peer);
            } else if (wid == 7) {
                if (lane < 4) {
                    float lm = wred[lane];
#pragma unroll
                    for (int w = 1; w < 8; w++) lm = fmaxf(lm, wred[w * 4 + lane]);
                    maxbuf[bn * 32 + rank * 4 + lane] = lm;
                }
                __syncwarp();
                if (lane == 0) mbar_arrive_local(mbar);
            }
        }
    }
}

// ======================= launch =======================

extern "C" void kernel_launch(void* const* d_in, const int* in_sizes, int n_in,
                              void* d_out, int out_size)
{
    const float* pi = (const float*)d_in[0];
    const float* A  = (const float*)d_in[1];
    const float* E  = (const float*)d_in[2];
    const int*   x  = (const int*)d_in[3];
    const int*   T  = (const int*)d_in[4];
    float* out = (float*)d_out;

    cudaFuncSetAttribute(hmm_main, cudaFuncAttributeMaxDynamicSharedMemorySize,
                         SMEM_BYTES);

    k_logpi<<<1, 512>>>(pi);
    k_prepA<<<NST, 512>>>(A);
    k_prepE<<<NST, 512>>>(E);
    hmm_main<<<NGRP * RANKS, THREADS, SMEM_BYTES>>>(x, T, out);
}